// round 14
// baseline (speedup 1.0000x reference)
#include <cuda_runtime.h>

typedef unsigned long long ull;

#define NB 512
#define NS 1024
#define NL 64
#define NC 66
#define LN2 0.6931471805599453f

static __device__ __forceinline__ ull fma2_(ull a, ull b, ull c) {
    ull d; asm("fma.rn.f32x2 %0, %1, %2, %3;" : "=l"(d) : "l"(a), "l"(b), "l"(c)); return d;
}
static __device__ __forceinline__ ull add2_(ull a, ull b) {
    ull d; asm("add.rn.f32x2 %0, %1, %2;" : "=l"(d) : "l"(a), "l"(b)); return d;
}
static __device__ __forceinline__ ull pack2_(float lo, float hi) {
    ull d; asm("mov.b64 %0, {%1, %2};" : "=l"(d) : "f"(lo), "f"(hi)); return d;
}
static __device__ __forceinline__ float2 unpack2_(ull v) {
    float lo, hi; asm("mov.b64 {%0, %1}, %2;" : "=f"(lo), "=f"(hi) : "l"(v)); return make_float2(lo, hi);
}

__device__ float        g_partial[NB];
__device__ unsigned int g_done = 0;

__global__ void __launch_bounds__(128, 1)
crf_fwd_kernel(const float* __restrict__ pred,
               const int*   __restrict__ ref,
               const int*   __restrict__ seq_len,
               const float* __restrict__ trans,
               float*       __restrict__ out)
{
    __shared__ __align__(16) float qbuf[4][2][64];
    __shared__ int is_last;

    const int w = threadIdx.x >> 5;        // warp = chain
    const int l = threadIdx.x & 31;
    const int b = (blockIdx.x << 2) + w;
    const int j0 = 2 * l, j1 = 2 * l + 1;
    const int L = seq_len[b];

    // E columns for states j0, j1: 128 regs
    ull e0[32], e1[32];
#pragma unroll
    for (int k = 0; k < 32; ++k) {
        e0[k] = pack2_(__expf(trans[(2 * k) * NC + j0]), __expf(trans[(2 * k + 1) * NC + j0]));
        e1[k] = pack2_(__expf(trans[(2 * k) * NC + j1]), __expf(trans[(2 * k + 1) * NC + j1]));
    }
    const float Te0 = __expf(trans[j0 * NC + 65]);
    const float Te1 = __expf(trans[j1 * NC + 65]);

    const float* pb = pred + (size_t)b * NS * NL;
    const float2* p2 = (const float2*)pb;
    const int last = L - 1;

    // init: q1 = exp(pred[0] + T[start]); cur regs carry the live q pair
    float cur0 = __expf(pb[j0] + trans[64 * NC + j0]);
    float cur1 = __expf(pb[j1] + trans[64 * NC + j1]);
    int esum = 0;

    float* buf0 = qbuf[w][0];
    float* buf1 = qbuf[w][1];
    ((float2*)buf0)[l] = make_float2(cur0, cur1);   // q_1 in buf0

    // pred pipeline (depth 3): at top of step t, w0/w1 = exp(row[t-1]-4)
    float2 r1 = p2[(size_t)min(1, last) * 32 + l];
    float2 r2 = p2[(size_t)min(2, last) * 32 + l];
    float w0 = __expf(r1.x - 4.0f);
    float w1 = __expf(r1.y - 4.0f);
    r1 = r2;
    r2 = p2[(size_t)min(3, last) * 32 + l];

    __syncwarp(0xFFFFFFFFu);

// one chain step, compile-time buffers RP -> WP
#define STEP(RP, WP, T)                                                        \
    {                                                                          \
        const ulonglong2* rp2 = (const ulonglong2*)(RP);                       \
        ull a0 = 0, a1 = 0, a2 = 0, a3 = 0;                                    \
        ull c0 = 0, c1 = 0, c2 = 0, c3 = 0;                                    \
        _Pragma("unroll")                                                      \
        for (int k = 0; k < 8; ++k) {                                          \
            ulonglong2 v0 = rp2[2 * k];                                        \
            ulonglong2 v1 = rp2[2 * k + 1];                                    \
            a0 = fma2_(v0.x, e0[4 * k + 0], a0);                               \
            c0 = fma2_(v0.x, e1[4 * k + 0], c0);                               \
            a1 = fma2_(v0.y, e0[4 * k + 1], a1);                               \
            c1 = fma2_(v0.y, e1[4 * k + 1], c1);                               \
            a2 = fma2_(v1.x, e0[4 * k + 2], a2);                               \
            c2 = fma2_(v1.x, e1[4 * k + 2], c2);                               \
            a3 = fma2_(v1.y, e0[4 * k + 3], a3);                               \
            c3 = fma2_(v1.y, e1[4 * k + 3], c3);                               \
        }                                                                      \
        float2 fa = unpack2_(add2_(add2_(a0, a1), add2_(a2, a3)));             \
        float2 fc = unpack2_(add2_(add2_(c0, c1), add2_(c2, c3)));             \
        float d0 = (fa.x + fa.y) * w0;                                         \
        float d1 = (fc.x + fc.y) * w1;                                         \
        if (((T) & 15) == 0) {        /* renorm: exact power of 2 */           \
            float m = (RP)[0];                                                 \
            int e = ((__float_as_int(m) >> 23) & 0xFF) - 127;                  \
            e = max(-100, min(100, e));                                        \
            float f = __int_as_float((unsigned)(127 - e) << 23);               \
            d0 *= f; d1 *= f;                                                  \
            esum += e;                                                         \
        }                                                                      \
        cur0 = d0; cur1 = d1;                                                  \
        ((float2*)(WP))[l] = make_float2(d0, d1);                              \
        w0 = __expf(r1.x - 4.0f);                                              \
        w1 = __expf(r1.y - 4.0f);                                              \
        r1 = r2;                                                               \
        r2 = p2[(size_t)min((T) + 2, last) * 32 + l];                          \
        asm volatile("prefetch.global.L2 [%0];"                                \
                     :: "l"(p2 + (size_t)min((T) + 6, last) * 32 + l));        \
        __syncwarp(0xFFFFFFFFu);                                               \
    }

    int t = 2;
    for (; t + 1 <= L; t += 2) {
        STEP(buf0, buf1, t);
        STEP(buf1, buf0, t + 1);
    }
    if (t <= L) {
        STEP(buf0, buf1, t);
    }
#undef STEP

    // terminal capture after the loop (cur = q_L; covers L==1 via init)
    float v = cur0 * Te0 + cur1 * Te1;

    // ---- real path score: uniform-trip gather, all lanes in every shfl ----
    float rsum = 0.0f;
    const int* rb = ref + (size_t)b * NS;
#pragma unroll 4
    for (int s0 = 0; s0 < L; s0 += 32) {
        int s  = s0 + l;
        bool ok = (s < L);
        int r  = ok ? rb[s] : 0;
        int pr = __shfl_up_sync(0xFFFFFFFFu, r, 1);          // all lanes participate
        if (l == 0) pr = (s0 == 0) ? 64 : rb[s0 - 1];
        if (ok) rsum += pb[(size_t)s * NL + r] + trans[pr * NC + r];
    }
    if (l == 0) rsum += trans[rb[L - 1] * NC + 65];

    // ---- in-warp reduction; per-chain partial ----
#pragma unroll
    for (int o = 16; o; o >>= 1) {
        v    += __shfl_xor_sync(0xFFFFFFFFu, v, o);
        rsum += __shfl_xor_sync(0xFFFFFFFFu, rsum, o);
    }
    if (l == 0)
        g_partial[b] = 4.0f * (float)(L - 1) + LN2 * (float)esum + __logf(v) - rsum;

    // ---- last CTA reduces all 512 partials ----
    __syncthreads();
    if (threadIdx.x == 0) {
        __threadfence();
        unsigned int prev = atomicAdd(&g_done, 1u);
        is_last = (prev == (unsigned)(gridDim.x - 1)) ? 1 : 0;
    }
    __syncthreads();
    if (is_last && w == 0) {
        __threadfence();
        float s = 0.0f;
#pragma unroll
        for (int i = 0; i < NB / 32; ++i)
            s += __ldcg(&g_partial[l + 32 * i]);
#pragma unroll
        for (int o = 16; o; o >>= 1)
            s += __shfl_xor_sync(0xFFFFFFFFu, s, o);
        if (l == 0) {
            out[0] = s;
            atomicExch(&g_done, 0u);   // reset for next graph replay
        }
    }
}

extern "C" void kernel_launch(void* const* d_in, const int* in_sizes, int n_in,
                              void* d_out, int out_size)
{
    const float* pred  = (const float*)d_in[0];
    const int*   refp  = (const int*)d_in[1];
    const int*   seq   = (const int*)d_in[2];
    const float* trans = (const float*)d_in[3];
    float* outp = (float*)d_out;

    crf_fwd_kernel<<<NB / 4, 128>>>(pred, refp, seq, trans, outp);
}

// round 15
// speedup vs baseline: 1.0054x; 1.0054x over previous
#include <cuda_runtime.h>

typedef unsigned long long ull;

#define NB 512
#define NS 1024
#define NL 64
#define NC 66
#define LN2 0.6931471805599453f

static __device__ __forceinline__ ull fma2_(ull a, ull b, ull c) {
    ull d; asm("fma.rn.f32x2 %0, %1, %2, %3;" : "=l"(d) : "l"(a), "l"(b), "l"(c)); return d;
}
static __device__ __forceinline__ ull add2_(ull a, ull b) {
    ull d; asm("add.rn.f32x2 %0, %1, %2;" : "=l"(d) : "l"(a), "l"(b)); return d;
}
static __device__ __forceinline__ ull pack2_(float lo, float hi) {
    ull d; asm("mov.b64 %0, {%1, %2};" : "=l"(d) : "f"(lo), "f"(hi)); return d;
}
static __device__ __forceinline__ float2 unpack2_(ull v) {
    float lo, hi; asm("mov.b64 {%0, %1}, %2;" : "=f"(lo), "=f"(hi) : "l"(v)); return make_float2(lo, hi);
}

__device__ float        g_partial[NB];
__device__ unsigned int g_done = 0;

__global__ void __launch_bounds__(128, 1)
crf_fwd_kernel(const float* __restrict__ pred,
               const int*   __restrict__ ref,
               const int*   __restrict__ seq_len,
               const float* __restrict__ trans,
               float*       __restrict__ out)
{
    __shared__ __align__(16) float qbuf[4][2][64];
    __shared__ int is_last;

    const int w = threadIdx.x >> 5;        // warp = chain
    const int l = threadIdx.x & 31;
    const int b = (blockIdx.x << 2) + w;
    const int j0 = 2 * l, j1 = 2 * l + 1;
    const int L = seq_len[b];

    // E columns for states j0, j1: 128 regs
    ull e0[32], e1[32];
#pragma unroll
    for (int k = 0; k < 32; ++k) {
        e0[k] = pack2_(__expf(trans[(2 * k) * NC + j0]), __expf(trans[(2 * k + 1) * NC + j0]));
        e1[k] = pack2_(__expf(trans[(2 * k) * NC + j1]), __expf(trans[(2 * k + 1) * NC + j1]));
    }
    const float Te0 = __expf(trans[j0 * NC + 65]);
    const float Te1 = __expf(trans[j1 * NC + 65]);

    const float* pb = pred + (size_t)b * NS * NL;
    const float2* p2 = (const float2*)pb;
    const int last = L - 1;

    // init: q1 = exp(pred[0] + T[start]); cur regs carry the live q pair
    float cur0 = __expf(pb[j0] + trans[64 * NC + j0]);
    float cur1 = __expf(pb[j1] + trans[64 * NC + j1]);
    int esum = 0;

    float* buf0 = qbuf[w][0];
    float* buf1 = qbuf[w][1];
    ((float2*)buf0)[l] = make_float2(cur0, cur1);   // q_1 in buf0

    // pipeline invariant at entry of step t: r1 = row[t-1], r2 = row[t]
    float2 r1 = p2[(size_t)min(1, last) * 32 + l];
    float2 r2 = p2[(size_t)min(2, last) * 32 + l];

    __syncwarp(0xFFFFFFFFu);

// one chain step, compile-time buffers RP -> WP.
// Order: (1) LDS batch, (2) pipeline rotate in the LDS shadow, (3) FFMA, (4) tail+STS, (5) sync.
#define STEP(RP, WP, T)                                                        \
    {                                                                          \
        const ulonglong2* rp2 = (const ulonglong2*)(RP);                       \
        /* (1) issue all q loads first */                                      \
        ulonglong2 qv0 = rp2[0],  qv1 = rp2[1],  qv2 = rp2[2],  qv3 = rp2[3];  \
        ulonglong2 qv4 = rp2[4],  qv5 = rp2[5],  qv6 = rp2[6],  qv7 = rp2[7];  \
        ulonglong2 qv8 = rp2[8],  qv9 = rp2[9],  qvA = rp2[10], qvB = rp2[11]; \
        ulonglong2 qvC = rp2[12], qvD = rp2[13], qvE = rp2[14], qvF = rp2[15]; \
        /* (2) rotation executes while LDS results are in flight */            \
        float w0 = __expf(r1.x - 4.0f);                                        \
        float w1 = __expf(r1.y - 4.0f);                                        \
        r1 = r2;                                                               \
        r2 = p2[(size_t)min((T) + 1, last) * 32 + l];                          \
        asm volatile("prefetch.global.L2 [%0];"                                \
                     :: "l"(p2 + (size_t)min((T) + 5, last) * 32 + l));        \
        /* (3) dual matvec, 8 accumulators */                                  \
        ull a0 = 0, a1 = 0, a2 = 0, a3 = 0;                                    \
        ull c0 = 0, c1 = 0, c2 = 0, c3 = 0;                                    \
        a0 = fma2_(qv0.x, e0[0],  a0);  c0 = fma2_(qv0.x, e1[0],  c0);         \
        a1 = fma2_(qv0.y, e0[1],  a1);  c1 = fma2_(qv0.y, e1[1],  c1);         \
        a2 = fma2_(qv1.x, e0[2],  a2);  c2 = fma2_(qv1.x, e1[2],  c2);         \
        a3 = fma2_(qv1.y, e0[3],  a3);  c3 = fma2_(qv1.y, e1[3],  c3);         \
        a0 = fma2_(qv2.x, e0[4],  a0);  c0 = fma2_(qv2.x, e1[4],  c0);         \
        a1 = fma2_(qv2.y, e0[5],  a1);  c1 = fma2_(qv2.y, e1[5],  c1);         \
        a2 = fma2_(qv3.x, e0[6],  a2);  c2 = fma2_(qv3.x, e1[6],  c2);         \
        a3 = fma2_(qv3.y, e0[7],  a3);  c3 = fma2_(qv3.y, e1[7],  c3);         \
        a0 = fma2_(qv4.x, e0[8],  a0);  c0 = fma2_(qv4.x, e1[8],  c0);         \
        a1 = fma2_(qv4.y, e0[9],  a1);  c1 = fma2_(qv4.y, e1[9],  c1);         \
        a2 = fma2_(qv5.x, e0[10], a2);  c2 = fma2_(qv5.x, e1[10], c2);         \
        a3 = fma2_(qv5.y, e0[11], a3);  c3 = fma2_(qv5.y, e1[11], c3);         \
        a0 = fma2_(qv6.x, e0[12], a0);  c0 = fma2_(qv6.x, e1[12], c0);         \
        a1 = fma2_(qv6.y, e0[13], a1);  c1 = fma2_(qv6.y, e1[13], c1);         \
        a2 = fma2_(qv7.x, e0[14], a2);  c2 = fma2_(qv7.x, e1[14], c2);         \
        a3 = fma2_(qv7.y, e0[15], a3);  c3 = fma2_(qv7.y, e1[15], c3);         \
        a0 = fma2_(qv8.x, e0[16], a0);  c0 = fma2_(qv8.x, e1[16], c0);         \
        a1 = fma2_(qv8.y, e0[17], a1);  c1 = fma2_(qv8.y, e1[17], c1);         \
        a2 = fma2_(qv9.x, e0[18], a2);  c2 = fma2_(qv9.x, e1[18], c2);         \
        a3 = fma2_(qv9.y, e0[19], a3);  c3 = fma2_(qv9.y, e1[19], c3);         \
        a0 = fma2_(qvA.x, e0[20], a0);  c0 = fma2_(qvA.x, e1[20], c0);         \
        a1 = fma2_(qvA.y, e0[21], a1);  c1 = fma2_(qvA.y, e1[21], c1);         \
        a2 = fma2_(qvB.x, e0[22], a2);  c2 = fma2_(qvB.x, e1[22], c2);         \
        a3 = fma2_(qvB.y, e0[23], a3);  c3 = fma2_(qvB.y, e1[23], c3);         \
        a0 = fma2_(qvC.x, e0[24], a0);  c0 = fma2_(qvC.x, e1[24], c0);         \
        a1 = fma2_(qvC.y, e0[25], a1);  c1 = fma2_(qvC.y, e1[25], c1);         \
        a2 = fma2_(qvD.x, e0[26], a2);  c2 = fma2_(qvD.x, e1[26], c2);         \
        a3 = fma2_(qvD.y, e0[27], a3);  c3 = fma2_(qvD.y, e1[27], c3);         \
        a0 = fma2_(qvE.x, e0[28], a0);  c0 = fma2_(qvE.x, e1[28], c0);         \
        a1 = fma2_(qvE.y, e0[29], a1);  c1 = fma2_(qvE.y, e1[29], c1);         \
        a2 = fma2_(qvF.x, e0[30], a2);  c2 = fma2_(qvF.x, e1[30], c2);         \
        a3 = fma2_(qvF.y, e0[31], a3);  c3 = fma2_(qvF.y, e1[31], c3);         \
        float2 fa = unpack2_(add2_(add2_(a0, a1), add2_(a2, a3)));             \
        float2 fc = unpack2_(add2_(add2_(c0, c1), add2_(c2, c3)));             \
        float d0 = (fa.x + fa.y) * w0;                                         \
        float d1 = (fc.x + fc.y) * w1;                                         \
        if (((T) & 15) == 0) {        /* renorm: exact power of 2 */           \
            float m = (RP)[0];                                                 \
            int e = ((__float_as_int(m) >> 23) & 0xFF) - 127;                  \
            e = max(-100, min(100, e));                                        \
            float f = __int_as_float((unsigned)(127 - e) << 23);               \
            d0 *= f; d1 *= f;                                                  \
            esum += e;                                                         \
        }                                                                      \
        cur0 = d0; cur1 = d1;                                                  \
        ((float2*)(WP))[l] = make_float2(d0, d1);                              \
        __syncwarp(0xFFFFFFFFu);                                               \
    }

    int t = 2;
    for (; t + 1 <= L; t += 2) {
        STEP(buf0, buf1, t);
        STEP(buf1, buf0, t + 1);
    }
    if (t <= L) {
        STEP(buf0, buf1, t);
    }
#undef STEP

    // terminal capture after the loop (cur = q_L; covers L==1 via init)
    float v = cur0 * Te0 + cur1 * Te1;

    // ---- real path score (lane-strided gather) ----
    float rsum = 0.0f;
    const int* rb = ref + (size_t)b * NS;
    for (int s = l; s < L; s += 32) {
        int r = rb[s];
        int p = (s == 0) ? 64 : rb[s - 1];
        rsum += pb[(size_t)s * NL + r] + trans[p * NC + r];
    }
    if (l == 0) rsum += trans[rb[L - 1] * NC + 65];

    // ---- in-warp reduction; per-chain partial ----
#pragma unroll
    for (int o = 16; o; o >>= 1) {
        v    += __shfl_xor_sync(0xFFFFFFFFu, v, o);
        rsum += __shfl_xor_sync(0xFFFFFFFFu, rsum, o);
    }
    if (l == 0)
        g_partial[b] = 4.0f * (float)(L - 1) + LN2 * (float)esum + __logf(v) - rsum;

    // ---- last CTA reduces all 512 partials ----
    __syncthreads();
    if (threadIdx.x == 0) {
        __threadfence();
        unsigned int prev = atomicAdd(&g_done, 1u);
        is_last = (prev == (unsigned)(gridDim.x - 1)) ? 1 : 0;
    }
    __syncthreads();
    if (is_last && w == 0) {
        __threadfence();
        float s = 0.0f;
#pragma unroll
        for (int i = 0; i < NB / 32; ++i)
            s += __ldcg(&g_partial[l + 32 * i]);
#pragma unroll
        for (int o = 16; o; o >>= 1)
            s += __shfl_xor_sync(0xFFFFFFFFu, s, o);
        if (l == 0) {
            out[0] = s;
            atomicExch(&g_done, 0u);   // reset for next graph replay
        }
    }
}

extern "C" void kernel_launch(void* const* d_in, const int* in_sizes, int n_in,
                              void* d_out, int out_size)
{
    const float* pred  = (const float*)d_in[0];
    const int*   refp  = (const int*)d_in[1];
    const int*   seq   = (const int*)d_in[2];
    const float* trans = (const float*)d_in[3];
    float* outp = (float*)d_out;

    crf_fwd_kernel<<<NB / 4, 128>>>(pred, refp, seq, trans, outp);
}

// round 16
// speedup vs baseline: 1.0387x; 1.0332x over previous
#include <cuda_runtime.h>

typedef unsigned long long ull;

#define NB 512
#define NS 1024
#define NL 64
#define NC 66
#define LN2 0.6931471805599453f

static __device__ __forceinline__ ull fma2_(ull a, ull b, ull c) {
    ull d; asm("fma.rn.f32x2 %0, %1, %2, %3;" : "=l"(d) : "l"(a), "l"(b), "l"(c)); return d;
}
static __device__ __forceinline__ ull add2_(ull a, ull b) {
    ull d; asm("add.rn.f32x2 %0, %1, %2;" : "=l"(d) : "l"(a), "l"(b)); return d;
}
static __device__ __forceinline__ ull pack2_(float lo, float hi) {
    ull d; asm("mov.b64 %0, {%1, %2};" : "=l"(d) : "f"(lo), "f"(hi)); return d;
}
static __device__ __forceinline__ float2 unpack2_(ull v) {
    float lo, hi; asm("mov.b64 {%0, %1}, %2;" : "=f"(lo), "=f"(hi) : "l"(v)); return make_float2(lo, hi);
}

__global__ void zero_out_kernel(float* out) { out[0] = 0.0f; }

__global__ void __launch_bounds__(128, 1)
crf_fwd_kernel(const float* __restrict__ pred,
               const int*   __restrict__ ref,
               const int*   __restrict__ seq_len,
               const float* __restrict__ trans,
               float*       __restrict__ out)
{
    // per-warp q double buffer: 4 warps x 2 bufs x 64 floats
    __shared__ __align__(16) float qbuf[4][2][64];

    const int w = threadIdx.x >> 5;        // warp in CTA: one chain each
    const int l = threadIdx.x & 31;        // lane
    const int b = (blockIdx.x << 2) + w;   // batch 0..511
    const int j0 = 2 * l, j1 = 2 * l + 1;  // the two states this thread owns
    const int L = seq_len[b];

    // E columns for states j0, j1 packed as f32x2 pairs over input-state pairs
    ull e0[32], e1[32];
#pragma unroll
    for (int k = 0; k < 32; ++k) {
        e0[k] = pack2_(__expf(trans[(2 * k) * NC + j0]), __expf(trans[(2 * k + 1) * NC + j0]));
        e1[k] = pack2_(__expf(trans[(2 * k) * NC + j1]), __expf(trans[(2 * k + 1) * NC + j1]));
    }
    const float Te0 = __expf(trans[j0 * NC + 65]);
    const float Te1 = __expf(trans[j1 * NC + 65]);

    const float* pb = pred + (size_t)b * NS * NL;

    // init: q1 = exp(pred[0] + T[start])
    float q0 = __expf(pb[j0] + trans[64 * NC + j0]);
    float q1 = __expf(pb[j1] + trans[64 * NC + j1]);

    float v = q0 * Te0 + q1 * Te1;   // covers L == 1
    int ecap = 0, esum = 0;

    float* buf0 = qbuf[w][0];
    float* buf1 = qbuf[w][1];
    ((float2*)buf0)[l] = make_float2(q0, q1);   // q_1 in buf0

    // pred row pipeline: at top of step t, (w0,w1) = exp(row[t-1] - 4)
    const int last = L - 1;
    float2 r1 = ((const float2*)(pb + (size_t)min(1, last) * NL))[l];
    float2 r2 = ((const float2*)(pb + (size_t)min(2, last) * NL))[l];
    float w0 = __expf(r1.x - 4.0f);
    float w1 = __expf(r1.y - 4.0f);
    r1 = r2;
    r2 = ((const float2*)(pb + (size_t)min(3, last) * NL))[l];

    __syncwarp(0xFFFFFFFFu);

    for (int t = 2; t <= L; ++t) {
        // q_t goes into buffer (t&1)^1; q_{t-1} is in buffer (t&1)
        const float* rp = (t & 1) ? buf1 : buf0;
        float*       wp = (t & 1) ? buf0 : buf1;
        const ulonglong2* rp2 = (const ulonglong2*)rp;

        // d_j = sum_i q_{t-1}[i] * E[i][j] for j in {j0, j1}
        ull a0 = 0, a1 = 0, c0 = 0, c1 = 0;
#pragma unroll
        for (int k = 0; k < 16; ++k) {
            ulonglong2 qv = rp2[k];                 // broadcast LDS.128 (conflict-free)
            a0 = fma2_(qv.x, e0[2 * k],     a0);
            c0 = fma2_(qv.x, e1[2 * k],     c0);
            a1 = fma2_(qv.y, e0[2 * k + 1], a1);
            c1 = fma2_(qv.y, e1[2 * k + 1], c1);
        }
        float2 fa = unpack2_(add2_(a0, a1));
        float2 fc = unpack2_(add2_(c0, c1));
        float d0 = (fa.x + fa.y) * w0;
        float d1 = (fc.x + fc.y) * w1;

        // O(1) renorm every 8 steps (exact power of 2, uniform across warp)
        if ((t & 7) == 0) {
            float m = rp[0];
            int e = ((__float_as_int(m) >> 23) & 0xFF) - 127;
            e = max(-100, min(100, e));
            float f = __int_as_float((unsigned)(127 - e) << 23);  // 2^-e
            d0 *= f; d1 *= f;
            esum += e;
        }

        if (t == L) { v = d0 * Te0 + d1 * Te1; ecap = esum; }

        ((float2*)wp)[l] = make_float2(d0, d1);

        // off-critical-path: next weight + pred pipeline rotate + prefetch
        w0 = __expf(r1.x - 4.0f);
        w1 = __expf(r1.y - 4.0f);
        r1 = r2;
        r2 = ((const float2*)(pb + (size_t)min(t + 2, last) * NL))[l];
        asm volatile("prefetch.global.L2 [%0];" :: "l"(pb + (size_t)min(t + 6, last) * NL + j0));

        __syncwarp(0xFFFFFFFFu);
    }

    // ---- real path score (lane-strided gather, off the chain) ----
    float rsum = 0.0f;
    const int* rb = ref + (size_t)b * NS;
    for (int t = l; t < L; t += 32) {
        int r = rb[t];
        int p = (t == 0) ? 64 : rb[t - 1];
        rsum += pb[(size_t)t * NL + r] + trans[p * NC + r];
    }
    if (l == 0) rsum += trans[rb[L - 1] * NC + 65];

    // ---- in-warp reduction; one atomic per chain ----
#pragma unroll
    for (int o = 16; o; o >>= 1) {
        v    += __shfl_xor_sync(0xFFFFFFFFu, v, o);
        rsum += __shfl_xor_sync(0xFFFFFFFFu, rsum, o);
    }
    if (l == 0) {
        float contrib = 4.0f * (float)(L - 1) + LN2 * (float)ecap + __logf(v) - rsum;
        atomicAdd(out, contrib);
    }
}

extern "C" void kernel_launch(void* const* d_in, const int* in_sizes, int n_in,
                              void* d_out, int out_size)
{
    const float* pred  = (const float*)d_in[0];
    const int*   refp  = (const int*)d_in[1];
    const int*   seq   = (const int*)d_in[2];
    const float* trans = (const float*)d_in[3];
    float* outp = (float*)d_out;

    zero_out_kernel<<<1, 1>>>(outp);
    crf_fwd_kernel<<<NB / 4, 128>>>(pred, refp, seq, trans, outp);
}

// round 17
// speedup vs baseline: 1.0827x; 1.0423x over previous
#include <cuda_runtime.h>
#include <cuda_fp16.h>

#define NB 512
#define NS 1024
#define NL 64
#define NC 66
#define LN2 0.6931471805599453f

static __device__ __forceinline__ __half2 u2h(unsigned u) {
    __half2 h; *reinterpret_cast<unsigned*>(&h) = u; return h;
}

__global__ void zero_out_kernel(float* out) { out[0] = 0.0f; }

__global__ void __launch_bounds__(128, 1)
crf_fwd_kernel(const float* __restrict__ pred,
               const int*   __restrict__ ref,
               const int*   __restrict__ seq_len,
               const float* __restrict__ trans,
               float*       __restrict__ out)
{
    // per-warp q double buffer in fp16: 4 warps x 2 bufs x 64 halfs (128 B)
    __shared__ __align__(16) __half2 qbuf[4][2][32];

    const int w = threadIdx.x >> 5;        // warp = chain
    const int l = threadIdx.x & 31;        // lane
    const int b = (blockIdx.x << 2) + w;   // batch
    const int j0 = 2 * l, j1 = 2 * l + 1;  // my two states
    const int L = seq_len[b];

    // E columns in fp16 half2: e[k] = (E[2k][j], E[2k+1][j]) — 64 regs total
    __half2 e0[32], e1[32];
#pragma unroll
    for (int k = 0; k < 32; ++k) {
        e0[k] = __floats2half2_rn(__expf(trans[(2 * k) * NC + j0]),
                                  __expf(trans[(2 * k + 1) * NC + j0]));
        e1[k] = __floats2half2_rn(__expf(trans[(2 * k) * NC + j1]),
                                  __expf(trans[(2 * k + 1) * NC + j1]));
    }
    const float Te0 = __expf(trans[j0 * NC + 65]);
    const float Te1 = __expf(trans[j1 * NC + 65]);

    const float* pb = pred + (size_t)b * NS * NL;
    const float2* p2 = (const float2*)pb;
    const int last = L - 1;

    // init: q1 = exp(pred[0] + T[start]) in fp32
    float cur0 = __expf(pb[j0] + trans[64 * NC + j0]);
    float cur1 = __expf(pb[j1] + trans[64 * NC + j1]);
    int esum = 0;

    __half2* h0 = qbuf[w][0];
    __half2* h1 = qbuf[w][1];
    h0[l] = __floats2half2_rn(cur0, cur1);       // q_1 in buffer 0

    // every-step renorm scale, precomputed off the critical path (R7 pattern):
    // scale for step t derives from q_{t-1}[0] (lane 0's cur0)
    float mref = __shfl_sync(0xFFFFFFFFu, cur0, 0);
    int   e_nx = ((__float_as_int(mref) >> 23) & 0xFF) - 127;
    e_nx = max(-60, min(60, e_nx));
    float sc_nx = __int_as_float((unsigned)(127 - e_nx) << 23);   // 2^-e

    // pred pipeline (depth 3): at top of step t, w0/w1 = exp(row[t-1]-4)
    float2 r1 = p2[(size_t)min(1, last) * 32 + l];
    float2 r2 = p2[(size_t)min(2, last) * 32 + l];
    float w0 = __expf(r1.x - 4.0f);
    float w1 = __expf(r1.y - 4.0f);
    r1 = r2;
    r2 = p2[(size_t)min(3, last) * 32 + l];

    __syncwarp(0xFFFFFFFFu);

    for (int t = 2; t <= L; ++t) {
        const __half2* rp = (t & 1) ? h1 : h0;   // q_{t-1}
        __half2*       wp = (t & 1) ? h0 : h1;
        const uint4* rp4 = (const uint4*)rp;

        // current step's combined scale (renorm x weight), precomputed parts
        const float sw0 = w0 * sc_nx;
        const float sw1 = w1 * sc_nx;
        esum += e_nx;

        // dual matvec in fp16: 8 LDS.128 + 64 HFMA2 (rt2 pipe), 8 accumulators
        __half2 z = __floats2half2_rn(0.0f, 0.0f);
        __half2 a0 = z, a1 = z, a2 = z, a3 = z;
        __half2 c0 = z, c1 = z, c2 = z, c3 = z;
#pragma unroll
        for (int k = 0; k < 8; ++k) {
            uint4 u = rp4[k];
            __half2 q0h = u2h(u.x), q1h = u2h(u.y), q2h = u2h(u.z), q3h = u2h(u.w);
            a0 = __hfma2(q0h, e0[4 * k + 0], a0);
            c0 = __hfma2(q0h, e1[4 * k + 0], c0);
            a1 = __hfma2(q1h, e0[4 * k + 1], a1);
            c1 = __hfma2(q1h, e1[4 * k + 1], c1);
            a2 = __hfma2(q2h, e0[4 * k + 2], a2);
            c2 = __hfma2(q2h, e1[4 * k + 2], c2);
            a3 = __hfma2(q3h, e0[4 * k + 3], a3);
            c3 = __hfma2(q3h, e1[4 * k + 3], c3);
        }
        float2 fa = __half22float2(__hadd2(__hadd2(a0, a1), __hadd2(a2, a3)));
        float2 fc = __half22float2(__hadd2(__hadd2(c0, c1), __hadd2(c2, c3)));
        float d0 = (fa.x + fa.y) * sw0;
        float d1 = (fc.x + fc.y) * sw1;

        cur0 = d0; cur1 = d1;
        wp[l] = __floats2half2_rn(d0, d1);

        // ---- off the critical recurrence ----
        // next step's renorm scale from this step's q_t[0]
        mref = __shfl_sync(0xFFFFFFFFu, d0, 0);
        e_nx = ((__float_as_int(mref) >> 23) & 0xFF) - 127;
        e_nx = max(-60, min(60, e_nx));
        sc_nx = __int_as_float((unsigned)(127 - e_nx) << 23);

        // pred pipeline rotate + prefetch
        w0 = __expf(r1.x - 4.0f);
        w1 = __expf(r1.y - 4.0f);
        r1 = r2;
        r2 = p2[(size_t)min(t + 2, last) * 32 + l];
        asm volatile("prefetch.global.L2 [%0];" :: "l"(p2 + (size_t)min(t + 6, last) * 32 + l));

        __syncwarp(0xFFFFFFFFu);
    }

    // terminal capture after the loop (cur = q_L in fp32; covers L==1 via init)
    float v = cur0 * Te0 + cur1 * Te1;

    // ---- real path score (lane-strided gather) ----
    float rsum = 0.0f;
    const int* rb = ref + (size_t)b * NS;
    for (int s = l; s < L; s += 32) {
        int r = rb[s];
        int p = (s == 0) ? 64 : rb[s - 1];
        rsum += pb[(size_t)s * NL + r] + trans[p * NC + r];
    }
    if (l == 0) rsum += trans[rb[L - 1] * NC + 65];

    // ---- in-warp reduction; one atomic per chain ----
#pragma unroll
    for (int o = 16; o; o >>= 1) {
        v    += __shfl_xor_sync(0xFFFFFFFFu, v, o);
        rsum += __shfl_xor_sync(0xFFFFFFFFu, rsum, o);
    }
    if (l == 0) {
        float contrib = 4.0f * (float)(L - 1) + LN2 * (float)esum + __logf(v) - rsum;
        atomicAdd(out, contrib);
    }
}

extern "C" void kernel_launch(void* const* d_in, const int* in_sizes, int n_in,
                              void* d_out, int out_size)
{
    const float* pred  = (const float*)d_in[0];
    const int*   refp  = (const int*)d_in[1];
    const int*   seq   = (const int*)d_in[2];
    const float* trans = (const float*)d_in[3];
    float* outp = (float*)d_out;

    zero_out_kernel<<<1, 1>>>(outp);
    crf_fwd_kernel<<<NB / 4, 128>>>(pred, refp, seq, trans, outp);
}